// round 1
// baseline (speedup 1.0000x reference)
#include <cuda_runtime.h>
#include <cuda_bf16.h>
#include <math.h>

// Scratch buffers (no cudaMalloc allowed): qkv [4,2048,3072], attn [4,2048,1024]
__device__ float g_qkv[4L * 2048 * 3072];
__device__ float g_attn[4L * 2048 * 1024];

// ---------------------------------------------------------------------------
// C[M,N] = A[M,K] * B[N,K]^T   (row-major A, row-major B; i.e. NT gemm)
// 128x128 tile, BK=8, 256 threads, 8x8 per thread via float4.
// All dims are multiples of 128/8 for this problem: no bounds checks.
// ---------------------------------------------------------------------------
__global__ __launch_bounds__(256) void sgemm_nt(const float* __restrict__ A,
                                                const float* __restrict__ B,
                                                float* __restrict__ C,
                                                int M, int N, int K) {
    __shared__ __align__(16) float As[8][132];
    __shared__ __align__(16) float Bs[8][132];

    int tid = threadIdx.x;
    int bm = blockIdx.y * 128;
    int bn = blockIdx.x * 128;
    int lr = tid >> 1;          // 0..127 : row within tile
    int lk = (tid & 1) * 4;     // 0 or 4 : k-offset (float4)
    int ty = tid >> 4;          // 0..15
    int tx = tid & 15;          // 0..15

    const float* Ap = A + (size_t)(bm + lr) * K + lk;
    const float* Bp = B + (size_t)(bn + lr) * K + lk;

    float acc[8][8];
#pragma unroll
    for (int i = 0; i < 8; i++)
#pragma unroll
        for (int j = 0; j < 8; j++) acc[i][j] = 0.f;

    for (int k0 = 0; k0 < K; k0 += 8) {
        float4 av = *(const float4*)(Ap + k0);
        float4 bv = *(const float4*)(Bp + k0);
        As[lk + 0][lr] = av.x; As[lk + 1][lr] = av.y;
        As[lk + 2][lr] = av.z; As[lk + 3][lr] = av.w;
        Bs[lk + 0][lr] = bv.x; Bs[lk + 1][lr] = bv.y;
        Bs[lk + 2][lr] = bv.z; Bs[lk + 3][lr] = bv.w;
        __syncthreads();

#pragma unroll
        for (int k = 0; k < 8; k++) {
            float4 a0 = *(const float4*)&As[k][ty * 4];
            float4 a1 = *(const float4*)&As[k][ty * 4 + 64];
            float4 b0 = *(const float4*)&Bs[k][tx * 4];
            float4 b1 = *(const float4*)&Bs[k][tx * 4 + 64];
            float ar[8] = {a0.x, a0.y, a0.z, a0.w, a1.x, a1.y, a1.z, a1.w};
            float br[8] = {b0.x, b0.y, b0.z, b0.w, b1.x, b1.y, b1.z, b1.w};
#pragma unroll
            for (int i = 0; i < 8; i++)
#pragma unroll
                for (int j = 0; j < 8; j++) acc[i][j] += ar[i] * br[j];
        }
        __syncthreads();
    }

#pragma unroll
    for (int i = 0; i < 8; i++) {
        int row = bm + ty * 4 + (i & 3) + ((i < 4) ? 0 : 64);
        float4 c0 = make_float4(acc[i][0], acc[i][1], acc[i][2], acc[i][3]);
        float4 c1 = make_float4(acc[i][4], acc[i][5], acc[i][6], acc[i][7]);
        *(float4*)&C[(size_t)row * N + bn + tx * 4] = c0;
        *(float4*)&C[(size_t)row * N + bn + tx * 4 + 64] = c1;
    }
}

// ---------------------------------------------------------------------------
// Causal flash attention, fp32, hd=64.
// Block = one (b, h, 64-query tile). Key tiles of 32. 256 threads.
// Online softmax with smem row stats; O accumulator in registers (4 rows x 4 d).
// ---------------------------------------------------------------------------
__global__ __launch_bounds__(256) void attn_kernel(const float* __restrict__ qkv,
                                                   float* __restrict__ attn) {
    const int S = 2048, TD = 3072, D = 1024;

    __shared__ __align__(16) float Qs[64][68];   // [d][row], float4-aligned rows
    __shared__ __align__(16) float Ks[64][33];   // [d][j]
    __shared__ __align__(16) float Vs[32][64];   // [j][d]
    __shared__ __align__(16) float Ps[64][33];   // [row][j]
    __shared__ float m_s[64], l_s[64], f_s[64];

    int tid = threadIdx.x;
    int qt = blockIdx.x, h = blockIdx.y, b = blockIdx.z;
    int qbase = qt * 64;
    int ty = tid >> 4;   // 0..15 -> rows ty*4 + i
    int tx = tid & 15;   // 0..15

    // Load Q tile (transposed into smem)
    for (int e = tid; e < 64 * 64; e += 256) {
        int r = e >> 6, d = e & 63;
        Qs[d][r] = qkv[(size_t)(b * S + qbase + r) * TD + h * 64 + d];
    }
    if (tid < 64) { m_s[tid] = -1e30f; l_s[tid] = 0.f; }

    float o[4][4];
#pragma unroll
    for (int i = 0; i < 4; i++)
#pragma unroll
        for (int j = 0; j < 4; j++) o[i][j] = 0.f;
    __syncthreads();

    int ktmax = 2 * qt + 1;
    for (int kt = 0; kt <= ktmax; kt++) {
        int kb = kt * 32;
        // Load K (transposed) and V tiles
        for (int e = tid; e < 32 * 64; e += 256) {
            int j = e >> 6, d = e & 63;
            size_t base = (size_t)(b * S + kb + j) * TD + h * 64 + d;
            Ks[d][j] = qkv[base + 1024];
            Vs[j][d] = qkv[base + 2048];
        }
        __syncthreads();

        // S = Q K^T  (each thread: 4 rows x 2 key-cols)
        float s[4][2] = {{0.f, 0.f}, {0.f, 0.f}, {0.f, 0.f}, {0.f, 0.f}};
#pragma unroll 8
        for (int k = 0; k < 64; k++) {
            float4 a = *(const float4*)&Qs[k][ty * 4];
            float b0 = Ks[k][tx * 2], b1 = Ks[k][tx * 2 + 1];
            s[0][0] += a.x * b0; s[0][1] += a.x * b1;
            s[1][0] += a.y * b0; s[1][1] += a.y * b1;
            s[2][0] += a.z * b0; s[2][1] += a.z * b1;
            s[3][0] += a.w * b0; s[3][1] += a.w * b1;
        }
#pragma unroll
        for (int i = 0; i < 4; i++)
#pragma unroll
            for (int jj = 0; jj < 2; jj++) {
                int qg = qbase + ty * 4 + i;
                int kg = kb + tx * 2 + jj;
                Ps[ty * 4 + i][tx * 2 + jj] =
                    (kg <= qg) ? s[i][jj] * 0.125f : -1e30f;
            }
        __syncthreads();

        // Online softmax row update
        if (tid < 64) {
            float mo = m_s[tid], mx = mo;
#pragma unroll
            for (int j = 0; j < 32; j++) mx = fmaxf(mx, Ps[tid][j]);
            float f = __expf(mo - mx);
            float sum = 0.f;
#pragma unroll
            for (int j = 0; j < 32; j++) {
                float p = __expf(Ps[tid][j] - mx);
                Ps[tid][j] = p;
                sum += p;
            }
            l_s[tid] = l_s[tid] * f + sum;
            m_s[tid] = mx;
            f_s[tid] = f;
        }
        __syncthreads();

        // Rescale O, then O += P V
#pragma unroll
        for (int i = 0; i < 4; i++) {
            float f = f_s[ty * 4 + i];
            o[i][0] *= f; o[i][1] *= f; o[i][2] *= f; o[i][3] *= f;
        }
#pragma unroll 4
        for (int j = 0; j < 32; j++) {
            float4 v = *(const float4*)&Vs[j][tx * 4];
#pragma unroll
            for (int i = 0; i < 4; i++) {
                float p = Ps[ty * 4 + i][j];
                o[i][0] += p * v.x; o[i][1] += p * v.y;
                o[i][2] += p * v.z; o[i][3] += p * v.w;
            }
        }
        __syncthreads();
    }

    // Epilogue: normalize and write [B,S,D] with D = H*hd
#pragma unroll
    for (int i = 0; i < 4; i++) {
        float inv = 1.f / l_s[ty * 4 + i];
        float4 v = make_float4(o[i][0] * inv, o[i][1] * inv,
                               o[i][2] * inv, o[i][3] * inv);
        *(float4*)&attn[(size_t)(b * S + qbase + ty * 4 + i) * D + h * 64 + tx * 4] = v;
    }
}

extern "C" void kernel_launch(void* const* d_in, const int* in_sizes, int n_in,
                              void* d_out, int out_size) {
    const float* x    = (const float*)d_in[0];   // [4,2048,1024]
    const float* Wqkv = (const float*)d_in[1];   // [3072,1024]
    const float* Wout = (const float*)d_in[2];   // [1024,1024]
    float* out = (float*)d_out;                  // [4,2048,1024]

    float* qkv;
    float* attn;
    cudaGetSymbolAddress((void**)&qkv, g_qkv);
    cudaGetSymbolAddress((void**)&attn, g_attn);

    dim3 blk(256);
    // qkv = x @ Wqkv^T : [8192,1024] x [3072,1024]^T -> [8192,3072]
    sgemm_nt<<<dim3(3072 / 128, 8192 / 128), blk>>>(x, Wqkv, qkv, 8192, 3072, 1024);
    // causal MHA
    attn_kernel<<<dim3(32, 16, 4), blk>>>(qkv, attn);
    // out = attn @ Wout^T : [8192,1024] x [1024,1024]^T -> [8192,1024]
    sgemm_nt<<<dim3(1024 / 128, 8192 / 128), blk>>>(attn, Wout, out, 8192, 1024, 1024);
}

// round 2
// speedup vs baseline: 1.0001x; 1.0001x over previous
#include <cuda_runtime.h>
#include <cuda_bf16.h>
#include <math.h>

// Scratch buffers (no cudaMalloc allowed): qkv [4,2048,3072], attn [4,2048,1024]
__device__ float g_qkv[4L * 2048 * 3072];
__device__ float g_attn[4L * 2048 * 1024];

// ---------------------------------------------------------------------------
// C[M,N] = A[M,K] * B[N,K]^T   (row-major A, row-major B; i.e. NT gemm)
// 128x128 tile, BK=8, 256 threads, 8x8 per thread via float4.
// All dims are multiples of 128/8 for this problem: no bounds checks.
// ---------------------------------------------------------------------------
__global__ __launch_bounds__(256) void sgemm_nt(const float* __restrict__ A,
                                                const float* __restrict__ B,
                                                float* __restrict__ C,
                                                int M, int N, int K) {
    __shared__ __align__(16) float As[8][132];
    __shared__ __align__(16) float Bs[8][132];

    int tid = threadIdx.x;
    int bm = blockIdx.y * 128;
    int bn = blockIdx.x * 128;
    int lr = tid >> 1;          // 0..127 : row within tile
    int lk = (tid & 1) * 4;     // 0 or 4 : k-offset (float4)
    int ty = tid >> 4;          // 0..15
    int tx = tid & 15;          // 0..15

    const float* Ap = A + (size_t)(bm + lr) * K + lk;
    const float* Bp = B + (size_t)(bn + lr) * K + lk;

    float acc[8][8];
#pragma unroll
    for (int i = 0; i < 8; i++)
#pragma unroll
        for (int j = 0; j < 8; j++) acc[i][j] = 0.f;

    for (int k0 = 0; k0 < K; k0 += 8) {
        float4 av = *(const float4*)(Ap + k0);
        float4 bv = *(const float4*)(Bp + k0);
        As[lk + 0][lr] = av.x; As[lk + 1][lr] = av.y;
        As[lk + 2][lr] = av.z; As[lk + 3][lr] = av.w;
        Bs[lk + 0][lr] = bv.x; Bs[lk + 1][lr] = bv.y;
        Bs[lk + 2][lr] = bv.z; Bs[lk + 3][lr] = bv.w;
        __syncthreads();

#pragma unroll
        for (int k = 0; k < 8; k++) {
            float4 a0 = *(const float4*)&As[k][ty * 4];
            float4 a1 = *(const float4*)&As[k][ty * 4 + 64];
            float4 b0 = *(const float4*)&Bs[k][tx * 4];
            float4 b1 = *(const float4*)&Bs[k][tx * 4 + 64];
            float ar[8] = {a0.x, a0.y, a0.z, a0.w, a1.x, a1.y, a1.z, a1.w};
            float br[8] = {b0.x, b0.y, b0.z, b0.w, b1.x, b1.y, b1.z, b1.w};
#pragma unroll
            for (int i = 0; i < 8; i++)
#pragma unroll
                for (int j = 0; j < 8; j++) acc[i][j] += ar[i] * br[j];
        }
        __syncthreads();
    }

#pragma unroll
    for (int i = 0; i < 8; i++) {
        int row = bm + ty * 4 + (i & 3) + ((i < 4) ? 0 : 64);
        float4 c0 = make_float4(acc[i][0], acc[i][1], acc[i][2], acc[i][3]);
        float4 c1 = make_float4(acc[i][4], acc[i][5], acc[i][6], acc[i][7]);
        *(float4*)&C[(size_t)row * N + bn + tx * 4] = c0;
        *(float4*)&C[(size_t)row * N + bn + tx * 4 + 64] = c1;
    }
}

// ---------------------------------------------------------------------------
// Causal flash attention, fp32, hd=64.
// Block = one (b, h, 64-query tile). Key tiles of 32. 256 threads.
// Online softmax with smem row stats; O accumulator in registers (4 rows x 4 d).
// ---------------------------------------------------------------------------
__global__ __launch_bounds__(256) void attn_kernel(const float* __restrict__ qkv,
                                                   float* __restrict__ attn) {
    const int S = 2048, TD = 3072, D = 1024;

    __shared__ __align__(16) float Qs[64][68];   // [d][row], float4-aligned rows
    __shared__ __align__(16) float Ks[64][33];   // [d][j]
    __shared__ __align__(16) float Vs[32][64];   // [j][d]
    __shared__ __align__(16) float Ps[64][33];   // [row][j]
    __shared__ float m_s[64], l_s[64], f_s[64];

    int tid = threadIdx.x;
    int qt = blockIdx.x, h = blockIdx.y, b = blockIdx.z;
    int qbase = qt * 64;
    int ty = tid >> 4;   // 0..15 -> rows ty*4 + i
    int tx = tid & 15;   // 0..15

    // Load Q tile (transposed into smem)
    for (int e = tid; e < 64 * 64; e += 256) {
        int r = e >> 6, d = e & 63;
        Qs[d][r] = qkv[(size_t)(b * S + qbase + r) * TD + h * 64 + d];
    }
    if (tid < 64) { m_s[tid] = -1e30f; l_s[tid] = 0.f; }

    float o[4][4];
#pragma unroll
    for (int i = 0; i < 4; i++)
#pragma unroll
        for (int j = 0; j < 4; j++) o[i][j] = 0.f;
    __syncthreads();

    int ktmax = 2 * qt + 1;
    for (int kt = 0; kt <= ktmax; kt++) {
        int kb = kt * 32;
        // Load K (transposed) and V tiles
        for (int e = tid; e < 32 * 64; e += 256) {
            int j = e >> 6, d = e & 63;
            size_t base = (size_t)(b * S + kb + j) * TD + h * 64 + d;
            Ks[d][j] = qkv[base + 1024];
            Vs[j][d] = qkv[base + 2048];
        }
        __syncthreads();

        // S = Q K^T  (each thread: 4 rows x 2 key-cols)
        float s[4][2] = {{0.f, 0.f}, {0.f, 0.f}, {0.f, 0.f}, {0.f, 0.f}};
#pragma unroll 8
        for (int k = 0; k < 64; k++) {
            float4 a = *(const float4*)&Qs[k][ty * 4];
            float b0 = Ks[k][tx * 2], b1 = Ks[k][tx * 2 + 1];
            s[0][0] += a.x * b0; s[0][1] += a.x * b1;
            s[1][0] += a.y * b0; s[1][1] += a.y * b1;
            s[2][0] += a.z * b0; s[2][1] += a.z * b1;
            s[3][0] += a.w * b0; s[3][1] += a.w * b1;
        }
#pragma unroll
        for (int i = 0; i < 4; i++)
#pragma unroll
            for (int jj = 0; jj < 2; jj++) {
                int qg = qbase + ty * 4 + i;
                int kg = kb + tx * 2 + jj;
                Ps[ty * 4 + i][tx * 2 + jj] =
                    (kg <= qg) ? s[i][jj] * 0.125f : -1e30f;
            }
        __syncthreads();

        // Online softmax row update
        if (tid < 64) {
            float mo = m_s[tid], mx = mo;
#pragma unroll
            for (int j = 0; j < 32; j++) mx = fmaxf(mx, Ps[tid][j]);
            float f = __expf(mo - mx);
            float sum = 0.f;
#pragma unroll
            for (int j = 0; j < 32; j++) {
                float p = __expf(Ps[tid][j] - mx);
                Ps[tid][j] = p;
                sum += p;
            }
            l_s[tid] = l_s[tid] * f + sum;
            m_s[tid] = mx;
            f_s[tid] = f;
        }
        __syncthreads();

        // Rescale O, then O += P V
#pragma unroll
        for (int i = 0; i < 4; i++) {
            float f = f_s[ty * 4 + i];
            o[i][0] *= f; o[i][1] *= f; o[i][2] *= f; o[i][3] *= f;
        }
#pragma unroll 4
        for (int j = 0; j < 32; j++) {
            float4 v = *(const float4*)&Vs[j][tx * 4];
#pragma unroll
            for (int i = 0; i < 4; i++) {
                float p = Ps[ty * 4 + i][j];
                o[i][0] += p * v.x; o[i][1] += p * v.y;
                o[i][2] += p * v.z; o[i][3] += p * v.w;
            }
        }
        __syncthreads();
    }

    // Epilogue: normalize and write [B,S,D] with D = H*hd
#pragma unroll
    for (int i = 0; i < 4; i++) {
        float inv = 1.f / l_s[ty * 4 + i];
        float4 v = make_float4(o[i][0] * inv, o[i][1] * inv,
                               o[i][2] * inv, o[i][3] * inv);
        *(float4*)&attn[(size_t)(b * S + qbase + ty * 4 + i) * D + h * 64 + tx * 4] = v;
    }
}

extern "C" void kernel_launch(void* const* d_in, const int* in_sizes, int n_in,
                              void* d_out, int out_size) {
    const float* x    = (const float*)d_in[0];   // [4,2048,1024]
    const float* Wqkv = (const float*)d_in[1];   // [3072,1024]
    const float* Wout = (const float*)d_in[2];   // [1024,1024]
    float* out = (float*)d_out;                  // [4,2048,1024]

    float* qkv;
    float* attn;
    cudaGetSymbolAddress((void**)&qkv, g_qkv);
    cudaGetSymbolAddress((void**)&attn, g_attn);

    dim3 blk(256);
    // qkv = x @ Wqkv^T : [8192,1024] x [3072,1024]^T -> [8192,3072]
    sgemm_nt<<<dim3(3072 / 128, 8192 / 128), blk>>>(x, Wqkv, qkv, 8192, 3072, 1024);
    // causal MHA
    attn_kernel<<<dim3(32, 16, 4), blk>>>(qkv, attn);
    // out = attn @ Wout^T : [8192,1024] x [1024,1024]^T -> [8192,1024]
    sgemm_nt<<<dim3(1024 / 128, 8192 / 128), blk>>>(attn, Wout, out, 8192, 1024, 1024);
}

// round 9
// speedup vs baseline: 1.6460x; 1.6458x over previous
#include <cuda_runtime.h>
#include <cuda_bf16.h>
#include <math.h>
#include <cstdint>

// Scratch buffers (no cudaMalloc allowed): qkv [4,2048,3072], attn [4,2048,1024]
__device__ float g_qkv[4L * 2048 * 3072];
__device__ float g_attn[4L * 2048 * 1024];

// ===========================================================================
// helpers (sm_103 base target only — NO tcgen05/TMEM, harness ptxas
// compiles PTX with .target sm_103, arch-accelerated features unavailable)
// ===========================================================================
__device__ __forceinline__ uint32_t smem_to_u32(const void* p) {
    uint32_t a;
    asm("{ .reg .u64 t; cvta.to.shared.u64 t, %1; cvt.u32.u64 %0, t; }"
        : "=r"(a) : "l"(p));
    return a;
}

__device__ __forceinline__ void cp_async16(uint32_t dst, const void* src) {
    asm volatile("cp.async.cg.shared.global [%0], [%1], 16;" :: "r"(dst), "l"(src));
}
#define CP_COMMIT() asm volatile("cp.async.commit_group;" ::: "memory")
#define CP_WAIT(n)  asm volatile("cp.async.wait_group %0;" :: "n"(n) : "memory")

__device__ __forceinline__ uint32_t f2tf32(float f) {
    uint32_t r;
    asm("cvt.rna.tf32.f32 %0, %1;" : "=r"(r) : "f"(f));
    return r;
}

__device__ __forceinline__ void mma_tf32(float* c, const uint32_t* a,
                                         uint32_t b0, uint32_t b1) {
    asm volatile(
        "mma.sync.aligned.m16n8k8.row.col.f32.tf32.tf32.f32 "
        "{%0,%1,%2,%3}, {%4,%5,%6,%7}, {%8,%9}, {%0,%1,%2,%3};"
        : "+f"(c[0]), "+f"(c[1]), "+f"(c[2]), "+f"(c[3])
        : "r"(a[0]), "r"(a[1]), "r"(a[2]), "r"(a[3]), "r"(b0), "r"(b1));
}

// ===========================================================================
// tf32 mma.sync GEMM: C[M,N] = A[M,K] * B[N,K]^T  (row-major A, row-major B)
// CTA tile 128x128, BK=32, 256 threads (8 warps, warp tile 32m x 64n),
// double-buffered cp.async. Requires M%128==0, N%128==0, K%32==0.
// smem rows padded to 36 floats -> fragment gathers are bank-conflict-free.
// ===========================================================================
static constexpr int PAD_ROW = 36;                       // floats per smem row
static constexpr int TILE_F  = 128 * PAD_ROW;            // floats per tile (A or B)
static constexpr int BUF_F   = 2 * TILE_F;               // floats per stage (A+B)
static constexpr int GEMM_SMEM_BYTES = 2 * BUF_F * 4;    // 73728

__global__ __launch_bounds__(256) void gemm_mma(const float* __restrict__ A,
                                                const float* __restrict__ B,
                                                float* __restrict__ C,
                                                int M, int N, int K) {
    extern __shared__ float smem[];
    uint32_t sb = smem_to_u32(smem);

    int tid  = threadIdx.x;
    int wid  = tid >> 5;
    int lane = tid & 31;
    int gid  = lane >> 2;   // 0..7
    int tig  = lane & 3;    // 0..3
    int wm   = wid & 3;     // m slab (32 rows)
    int wn   = wid >> 2;    // n slab (64 cols)
    int bm   = blockIdx.y * 128;
    int bn   = blockIdx.x * 128;

    const int n_iters = K / 32;

    // per-stage smem base addresses (bytes) for cp.async
    auto load_tile = [&](int it, int buf) {
        uint32_t abase = sb + (uint32_t)buf * (BUF_F * 4);
        uint32_t bbase = abase + TILE_F * 4;
        const char* Ab = (const char*)(A + (size_t)bm * K + (size_t)it * 32);
        const char* Bb = (const char*)(B + (size_t)bn * K + (size_t)it * 32);
#pragma unroll
        for (int i = 0; i < 4; i++) {
            int ch  = tid + i * 256;          // 0..1023
            int r   = ch >> 3;                // row 0..127
            int c16 = (ch & 7) * 16;          // 16B chunk within 128B row
            cp_async16(abase + r * (PAD_ROW * 4) + c16,
                       Ab + (size_t)r * K * 4 + c16);
            cp_async16(bbase + r * (PAD_ROW * 4) + c16,
                       Bb + (size_t)r * K * 4 + c16);
        }
        CP_COMMIT();
    };

    float acc[2][8][4];
#pragma unroll
    for (int mt = 0; mt < 2; mt++)
#pragma unroll
        for (int nt = 0; nt < 8; nt++)
#pragma unroll
            for (int j = 0; j < 4; j++) acc[mt][nt][j] = 0.f;

    load_tile(0, 0);

    for (int it = 0; it < n_iters; it++) {
        int buf = it & 1;
        if (it + 1 < n_iters) {
            load_tile(it + 1, buf ^ 1);
            CP_WAIT(1);
        } else {
            CP_WAIT(0);
        }
        __syncthreads();

        const float* As = smem + buf * BUF_F;
        const float* Bs = As + TILE_F;

#pragma unroll
        for (int ks = 0; ks < 4; ks++) {
            int kc = ks * 8 + tig;
            uint32_t a[2][4];
#pragma unroll
            for (int mt = 0; mt < 2; mt++) {
                int r0 = wm * 32 + mt * 16 + gid;
                a[mt][0] = f2tf32(As[r0 * PAD_ROW + kc]);
                a[mt][1] = f2tf32(As[(r0 + 8) * PAD_ROW + kc]);
                a[mt][2] = f2tf32(As[r0 * PAD_ROW + kc + 4]);
                a[mt][3] = f2tf32(As[(r0 + 8) * PAD_ROW + kc + 4]);
            }
#pragma unroll
            for (int nt = 0; nt < 8; nt++) {
                int rn = wn * 64 + nt * 8 + gid;
                uint32_t b0 = f2tf32(Bs[rn * PAD_ROW + kc]);
                uint32_t b1 = f2tf32(Bs[rn * PAD_ROW + kc + 4]);
                mma_tf32(acc[0][nt], a[0], b0, b1);
                mma_tf32(acc[1][nt], a[1], b0, b1);
            }
        }
        __syncthreads();   // protect buffer from next iteration's prefetch
    }

    // epilogue: c0,c1 -> (row, col..col+1); c2,c3 -> (row+8, col..col+1)
#pragma unroll
    for (int mt = 0; mt < 2; mt++) {
        int row = bm + wm * 32 + mt * 16 + gid;
#pragma unroll
        for (int nt = 0; nt < 8; nt++) {
            int col = bn + wn * 64 + nt * 8 + tig * 2;
            *(float2*)&C[(size_t)row * N + col] =
                make_float2(acc[mt][nt][0], acc[mt][nt][1]);
            *(float2*)&C[(size_t)(row + 8) * N + col] =
                make_float2(acc[mt][nt][2], acc[mt][nt][3]);
        }
    }
}

// ---------------------------------------------------------------------------
// Causal flash attention, fp32, hd=64 (unchanged, proven).
// ---------------------------------------------------------------------------
__global__ __launch_bounds__(256) void attn_kernel(const float* __restrict__ qkv,
                                                   float* __restrict__ attn) {
    const int S = 2048, TD = 3072, D = 1024;

    __shared__ __align__(16) float Qs[64][68];
    __shared__ __align__(16) float Ks[64][33];
    __shared__ __align__(16) float Vs[32][64];
    __shared__ __align__(16) float Ps[64][33];
    __shared__ float m_s[64], l_s[64], f_s[64];

    int tid = threadIdx.x;
    int qt = blockIdx.x, h = blockIdx.y, b = blockIdx.z;
    int qbase = qt * 64;
    int ty = tid >> 4;
    int tx = tid & 15;

    for (int e = tid; e < 64 * 64; e += 256) {
        int r = e >> 6, d = e & 63;
        Qs[d][r] = qkv[(size_t)(b * S + qbase + r) * TD + h * 64 + d];
    }
    if (tid < 64) { m_s[tid] = -1e30f; l_s[tid] = 0.f; }

    float o[4][4];
#pragma unroll
    for (int i = 0; i < 4; i++)
#pragma unroll
        for (int j = 0; j < 4; j++) o[i][j] = 0.f;
    __syncthreads();

    int ktmax = 2 * qt + 1;
    for (int kt = 0; kt <= ktmax; kt++) {
        int kb = kt * 32;
        for (int e = tid; e < 32 * 64; e += 256) {
            int j = e >> 6, d = e & 63;
            size_t base = (size_t)(b * S + kb + j) * TD + h * 64 + d;
            Ks[d][j] = qkv[base + 1024];
            Vs[j][d] = qkv[base + 2048];
        }
        __syncthreads();

        float s[4][2] = {{0.f, 0.f}, {0.f, 0.f}, {0.f, 0.f}, {0.f, 0.f}};
#pragma unroll 8
        for (int k = 0; k < 64; k++) {
            float4 a = *(const float4*)&Qs[k][ty * 4];
            float b0 = Ks[k][tx * 2], b1 = Ks[k][tx * 2 + 1];
            s[0][0] += a.x * b0; s[0][1] += a.x * b1;
            s[1][0] += a.y * b0; s[1][1] += a.y * b1;
            s[2][0] += a.z * b0; s[2][1] += a.z * b1;
            s[3][0] += a.w * b0; s[3][1] += a.w * b1;
        }
#pragma unroll
        for (int i = 0; i < 4; i++)
#pragma unroll
            for (int jj = 0; jj < 2; jj++) {
                int qg = qbase + ty * 4 + i;
                int kg = kb + tx * 2 + jj;
                Ps[ty * 4 + i][tx * 2 + jj] =
                    (kg <= qg) ? s[i][jj] * 0.125f : -1e30f;
            }
        __syncthreads();

        if (tid < 64) {
            float mo = m_s[tid], mx = mo;
#pragma unroll
            for (int j = 0; j < 32; j++) mx = fmaxf(mx, Ps[tid][j]);
            float f = __expf(mo - mx);
            float sum = 0.f;
#pragma unroll
            for (int j = 0; j < 32; j++) {
                float p = __expf(Ps[tid][j] - mx);
                Ps[tid][j] = p;
                sum += p;
            }
            l_s[tid] = l_s[tid] * f + sum;
            m_s[tid] = mx;
            f_s[tid] = f;
        }
        __syncthreads();

#pragma unroll
        for (int i = 0; i < 4; i++) {
            float f = f_s[ty * 4 + i];
            o[i][0] *= f; o[i][1] *= f; o[i][2] *= f; o[i][3] *= f;
        }
#pragma unroll 4
        for (int j = 0; j < 32; j++) {
            float4 v = *(const float4*)&Vs[j][tx * 4];
#pragma unroll
            for (int i = 0; i < 4; i++) {
                float p = Ps[ty * 4 + i][j];
                o[i][0] += p * v.x; o[i][1] += p * v.y;
                o[i][2] += p * v.z; o[i][3] += p * v.w;
            }
        }
        __syncthreads();
    }

#pragma unroll
    for (int i = 0; i < 4; i++) {
        float inv = 1.f / l_s[ty * 4 + i];
        float4 v = make_float4(o[i][0] * inv, o[i][1] * inv,
                               o[i][2] * inv, o[i][3] * inv);
        *(float4*)&attn[(size_t)(b * S + qbase + ty * 4 + i) * D + h * 64 + tx * 4] = v;
    }
}

extern "C" void kernel_launch(void* const* d_in, const int* in_sizes, int n_in,
                              void* d_out, int out_size) {
    const float* x    = (const float*)d_in[0];   // [4,2048,1024]
    const float* Wqkv = (const float*)d_in[1];   // [3072,1024]
    const float* Wout = (const float*)d_in[2];   // [1024,1024]
    float* out = (float*)d_out;                  // [4,2048,1024]

    float* qkv;
    float* attn;
    cudaGetSymbolAddress((void**)&qkv, g_qkv);
    cudaGetSymbolAddress((void**)&attn, g_attn);

    cudaFuncSetAttribute(gemm_mma, cudaFuncAttributeMaxDynamicSharedMemorySize,
                         GEMM_SMEM_BYTES);

    // qkv = x @ Wqkv^T : [8192,1024] x [3072,1024]^T -> [8192,3072]
    gemm_mma<<<dim3(3072 / 128, 8192 / 128), 256, GEMM_SMEM_BYTES>>>(
        x, Wqkv, qkv, 8192, 3072, 1024);
    // causal MHA
    attn_kernel<<<dim3(32, 16, 4), 256>>>(qkv, attn);
    // out = attn @ Wout^T : [8192,1024] x [1024,1024]^T -> [8192,1024]
    gemm_mma<<<dim3(1024 / 128, 8192 / 128), 256, GEMM_SMEM_BYTES>>>(
        attn, Wout, out, 8192, 1024, 1024);
}

// round 12
// speedup vs baseline: 3.2725x; 1.9881x over previous
#include <cuda_runtime.h>
#include <cuda_bf16.h>
#include <math.h>
#include <cstdint>

// Scratch buffers (no cudaMalloc allowed): qkv [4,2048,3072], attn [4,2048,1024]
__device__ float g_qkv[4L * 2048 * 3072];
__device__ float g_attn[4L * 2048 * 1024];

// ===========================================================================
// helpers (sm_103 base target only — tcgen05/TMEM unavailable in this devloop)
// ===========================================================================
__device__ __forceinline__ uint32_t smem_to_u32(const void* p) {
    uint32_t a;
    asm("{ .reg .u64 t; cvta.to.shared.u64 t, %1; cvt.u32.u64 %0, t; }"
        : "=r"(a) : "l"(p));
    return a;
}

__device__ __forceinline__ void cp_async16(uint32_t dst, const void* src) {
    asm volatile("cp.async.cg.shared.global [%0], [%1], 16;" :: "r"(dst), "l"(src));
}
#define CP_COMMIT() asm volatile("cp.async.commit_group;" ::: "memory")
#define CP_WAIT(n)  asm volatile("cp.async.wait_group %0;" :: "n"(n) : "memory")

__device__ __forceinline__ uint32_t f2tf32(float f) {
    uint32_t r;
    asm("cvt.rna.tf32.f32 %0, %1;" : "=r"(r) : "f"(f));
    return r;
}

__device__ __forceinline__ void mma_tf32(float* c, const uint32_t* a,
                                         uint32_t b0, uint32_t b1) {
    asm volatile(
        "mma.sync.aligned.m16n8k8.row.col.f32.tf32.tf32.f32 "
        "{%0,%1,%2,%3}, {%4,%5,%6,%7}, {%8,%9}, {%0,%1,%2,%3};"
        : "+f"(c[0]), "+f"(c[1]), "+f"(c[2]), "+f"(c[3])
        : "r"(a[0]), "r"(a[1]), "r"(a[2]), "r"(a[3]), "r"(b0), "r"(b1));
}

// ===========================================================================
// tf32 mma.sync GEMM: C[M,N] = A[M,K] * B[N,K]^T  (row-major A, row-major B)
// CTA 128x128, BK=32, 256 threads (8 warps, 32m x 64n each), double-buffered.
// CVT_OUT=true stores C pre-rounded to tf32 (consumers feed mma directly).
// ===========================================================================
static constexpr int PAD_ROW = 36;
static constexpr int TILE_F  = 128 * PAD_ROW;
static constexpr int BUF_F   = 2 * TILE_F;
static constexpr int GEMM_SMEM_BYTES = 2 * BUF_F * 4;    // 73728

template <bool CVT_OUT>
__global__ __launch_bounds__(256) void gemm_mma(const float* __restrict__ A,
                                                const float* __restrict__ B,
                                                float* __restrict__ C,
                                                int M, int N, int K) {
    extern __shared__ float smem[];
    uint32_t sb = smem_to_u32(smem);

    int tid  = threadIdx.x;
    int wid  = tid >> 5;
    int lane = tid & 31;
    int gid  = lane >> 2;
    int tig  = lane & 3;
    int wm   = wid & 3;
    int wn   = wid >> 2;
    int bm   = blockIdx.y * 128;
    int bn   = blockIdx.x * 128;

    const int n_iters = K / 32;

    auto load_tile = [&](int it, int buf) {
        uint32_t abase = sb + (uint32_t)buf * (BUF_F * 4);
        uint32_t bbase = abase + TILE_F * 4;
        const char* Ab = (const char*)(A + (size_t)bm * K + (size_t)it * 32);
        const char* Bb = (const char*)(B + (size_t)bn * K + (size_t)it * 32);
#pragma unroll
        for (int i = 0; i < 4; i++) {
            int ch  = tid + i * 256;
            int r   = ch >> 3;
            int c16 = (ch & 7) * 16;
            cp_async16(abase + r * (PAD_ROW * 4) + c16,
                       Ab + (size_t)r * K * 4 + c16);
            cp_async16(bbase + r * (PAD_ROW * 4) + c16,
                       Bb + (size_t)r * K * 4 + c16);
        }
        CP_COMMIT();
    };

    float acc[2][8][4];
#pragma unroll
    for (int mt = 0; mt < 2; mt++)
#pragma unroll
        for (int nt = 0; nt < 8; nt++)
#pragma unroll
            for (int j = 0; j < 4; j++) acc[mt][nt][j] = 0.f;

    load_tile(0, 0);

    for (int it = 0; it < n_iters; it++) {
        int buf = it & 1;
        if (it + 1 < n_iters) {
            load_tile(it + 1, buf ^ 1);
            CP_WAIT(1);
        } else {
            CP_WAIT(0);
        }
        __syncthreads();

        const float* As = smem + buf * BUF_F;
        const float* Bs = As + TILE_F;

#pragma unroll
        for (int ks = 0; ks < 4; ks++) {
            int kc = ks * 8 + tig;
            uint32_t a[2][4];
#pragma unroll
            for (int mt = 0; mt < 2; mt++) {
                int r0 = wm * 32 + mt * 16 + gid;
                a[mt][0] = f2tf32(As[r0 * PAD_ROW + kc]);
                a[mt][1] = f2tf32(As[(r0 + 8) * PAD_ROW + kc]);
                a[mt][2] = f2tf32(As[r0 * PAD_ROW + kc + 4]);
                a[mt][3] = f2tf32(As[(r0 + 8) * PAD_ROW + kc + 4]);
            }
#pragma unroll
            for (int nt = 0; nt < 8; nt++) {
                int rn = wn * 64 + nt * 8 + gid;
                uint32_t b0 = f2tf32(Bs[rn * PAD_ROW + kc]);
                uint32_t b1 = f2tf32(Bs[rn * PAD_ROW + kc + 4]);
                mma_tf32(acc[0][nt], a[0], b0, b1);
                mma_tf32(acc[1][nt], a[1], b0, b1);
            }
        }
        __syncthreads();
    }

#pragma unroll
    for (int mt = 0; mt < 2; mt++) {
        int row = bm + wm * 32 + mt * 16 + gid;
#pragma unroll
        for (int nt = 0; nt < 8; nt++) {
            int col = bn + wn * 64 + nt * 8 + tig * 2;
            float v0 = acc[mt][nt][0], v1 = acc[mt][nt][1];
            float v2 = acc[mt][nt][2], v3 = acc[mt][nt][3];
            if (CVT_OUT) {
                v0 = __uint_as_float(f2tf32(v0));
                v1 = __uint_as_float(f2tf32(v1));
                v2 = __uint_as_float(f2tf32(v2));
                v3 = __uint_as_float(f2tf32(v3));
            }
            *(float2*)&C[(size_t)row * N + col] = make_float2(v0, v1);
            *(float2*)&C[(size_t)(row + 8) * N + col] = make_float2(v2, v3);
        }
    }
}

// ===========================================================================
// Causal flash attention with tf32 mma.sync. hd=64.
// Block: 128 q-rows x (b,h); 8 warps, warp owns 16 q-rows. K-tiles of 64.
// qkv is PRE-ROUNDED to tf32 by gemm_mma<true> -> raw bit loads, no cvt.
// smem pad 68 floats/row -> all fragment gathers conflict-free.
// ===========================================================================
static constexpr int APAD = 68;
static constexpr int ATT_QP_F = 128 * APAD;                 // Q tile, reused as P
static constexpr int ATT_K_F  = 64 * APAD;
static constexpr int ATT_SMEM_BYTES = (ATT_QP_F + 2 * ATT_K_F) * 4;   // 69632

__global__ __launch_bounds__(256, 2) void attn_mma(const float* __restrict__ qkv,
                                                   float* __restrict__ attn) {
    const int S = 2048, TD = 3072, D = 1024;
    extern __shared__ float sm[];
    float* QP = sm;                       // [128][68]: Q, then P
    float* Ks = sm + ATT_QP_F;            // [64][68]
    float* Vs = Ks + ATT_K_F;             // [64][68]
    const uint32_t* QPu = (const uint32_t*)QP;
    const uint32_t* Ksu = (const uint32_t*)Ks;
    const uint32_t* Vsu = (const uint32_t*)Vs;

    uint32_t sb = smem_to_u32(sm);
    const uint32_t sbK = sb + ATT_QP_F * 4;
    const uint32_t sbV = sbK + ATT_K_F * 4;

    int tid  = threadIdx.x;
    int wid  = tid >> 5;
    int lane = tid & 31;
    int gid  = lane >> 2;
    int tig  = lane & 3;
    int qt = blockIdx.x, h = blockIdx.y, b = blockIdx.z;
    int qbase = qt * 128;
    int r0 = wid * 16 + gid;              // local q row (and +8)

    // ---- load Q tile [128][64], coalesced cp.async ----
    {
        const char* Qg = (const char*)(qkv + (size_t)(b * S + qbase) * TD + h * 64);
#pragma unroll
        for (int i = 0; i < 8; i++) {
            int ch  = tid + i * 256;        // 0..2047
            int r   = ch >> 4;              // 0..127
            int c16 = (ch & 15) * 16;
            cp_async16(sb + r * (APAD * 4) + c16, Qg + (size_t)r * TD * 4 + c16);
        }
        CP_COMMIT();
        CP_WAIT(0);
        __syncthreads();
    }

    // ---- Q fragments (scale 1/8 folded in; x0.125 is exact on tf32) ----
    uint32_t qa[8][4];
#pragma unroll
    for (int ks = 0; ks < 8; ks++) {
        int kc = ks * 8 + tig;
        qa[ks][0] = __float_as_uint(0.125f * QP[r0 * APAD + kc]);
        qa[ks][1] = __float_as_uint(0.125f * QP[(r0 + 8) * APAD + kc]);
        qa[ks][2] = __float_as_uint(0.125f * QP[r0 * APAD + kc + 4]);
        qa[ks][3] = __float_as_uint(0.125f * QP[(r0 + 8) * APAD + kc + 4]);
    }
    __syncthreads();   // QP now free for P

    float oa[8][4];
#pragma unroll
    for (int nt = 0; nt < 8; nt++)
#pragma unroll
        for (int j = 0; j < 4; j++) oa[nt][j] = 0.f;
    float m0 = -1e30f, m1 = -1e30f, l0 = 0.f, l1 = 0.f;

    const int qg0 = qbase + r0;
    const int qg1 = qg0 + 8;
    const int ktmax = 2 * qt + 1;

    for (int kt = 0; kt <= ktmax; kt++) {
        int kb = kt * 64;
        __syncthreads();   // all warps done reading Ks/Vs/QP(P) of prev tile

        // ---- load K,V tiles [64][64] ----
        const char* Kg = (const char*)(qkv + (size_t)(b * S + kb) * TD + 1024 + h * 64);
        const char* Vg = (const char*)(qkv + (size_t)(b * S + kb) * TD + 2048 + h * 64);
#pragma unroll
        for (int i = 0; i < 4; i++) {
            int ch  = tid + i * 256;        // 0..1023
            int r   = ch >> 4;              // 0..63
            int c16 = (ch & 15) * 16;
            cp_async16(sbK + r * (APAD * 4) + c16, Kg + (size_t)r * TD * 4 + c16);
            cp_async16(sbV + r * (APAD * 4) + c16, Vg + (size_t)r * TD * 4 + c16);
        }
        CP_COMMIT();
        CP_WAIT(0);
        __syncthreads();

        // ---- S = (Q/8) K^T : warp 16x64 ----
        float sa[8][4];
#pragma unroll
        for (int nt = 0; nt < 8; nt++)
#pragma unroll
            for (int j = 0; j < 4; j++) sa[nt][j] = 0.f;
#pragma unroll
        for (int ks = 0; ks < 8; ks++) {
            int kc = ks * 8 + tig;
#pragma unroll
            for (int nt = 0; nt < 8; nt++) {
                int rn = nt * 8 + gid;
                uint32_t b0 = Ksu[rn * APAD + kc];
                uint32_t b1 = Ksu[rn * APAD + kc + 4];
                mma_tf32(sa[nt], qa[ks], b0, b1);
            }
        }

        // ---- causal mask (only tiles overlapping the diagonal) ----
        if (kt >= 2 * qt) {
#pragma unroll
            for (int nt = 0; nt < 8; nt++) {
                int kg = kb + nt * 8 + tig * 2;
                if (kg > qg0)     sa[nt][0] = -1e30f;
                if (kg + 1 > qg0) sa[nt][1] = -1e30f;
                if (kg > qg1)     sa[nt][2] = -1e30f;
                if (kg + 1 > qg1) sa[nt][3] = -1e30f;
            }
        }

        // ---- online softmax (rows r0, r0+8) ----
        float v0 = -1e30f, v1 = -1e30f;
#pragma unroll
        for (int nt = 0; nt < 8; nt++) {
            v0 = fmaxf(v0, fmaxf(sa[nt][0], sa[nt][1]));
            v1 = fmaxf(v1, fmaxf(sa[nt][2], sa[nt][3]));
        }
        v0 = fmaxf(v0, __shfl_xor_sync(0xffffffff, v0, 1));
        v0 = fmaxf(v0, __shfl_xor_sync(0xffffffff, v0, 2));
        v1 = fmaxf(v1, __shfl_xor_sync(0xffffffff, v1, 1));
        v1 = fmaxf(v1, __shfl_xor_sync(0xffffffff, v1, 2));
        float mn0 = fmaxf(m0, v0), mn1 = fmaxf(m1, v1);
        float f0 = __expf(m0 - mn0), f1 = __expf(m1 - mn1);
        m0 = mn0; m1 = mn1;

        float ls0 = 0.f, ls1 = 0.f;
#pragma unroll
        for (int nt = 0; nt < 8; nt++) {
            int col = nt * 8 + tig * 2;
            float p00 = __expf(sa[nt][0] - mn0);
            float p01 = __expf(sa[nt][1] - mn0);
            float p10 = __expf(sa[nt][2] - mn1);
            float p11 = __expf(sa[nt][3] - mn1);
            ls0 += p00 + p01;
            ls1 += p10 + p11;
            QP[r0 * APAD + col]       = __uint_as_float(f2tf32(p00));
            QP[r0 * APAD + col + 1]   = __uint_as_float(f2tf32(p01));
            QP[(r0 + 8) * APAD + col]     = __uint_as_float(f2tf32(p10));
            QP[(r0 + 8) * APAD + col + 1] = __uint_as_float(f2tf32(p11));
        }
        l0 = l0 * f0 + ls0;
        l1 = l1 * f1 + ls1;
#pragma unroll
        for (int nt = 0; nt < 8; nt++) {
            oa[nt][0] *= f0; oa[nt][1] *= f0;
            oa[nt][2] *= f1; oa[nt][3] *= f1;
        }
        __syncwarp();   // P rows of this warp visible to its own lanes

        // ---- O += P V : warp 16x64, K=64 keys ----
#pragma unroll
        for (int ks = 0; ks < 8; ks++) {
            int kc = ks * 8 + tig;          // key index in tile
            uint32_t pa[4];
            pa[0] = QPu[r0 * APAD + kc];
            pa[1] = QPu[(r0 + 8) * APAD + kc];
            pa[2] = QPu[r0 * APAD + kc + 4];
            pa[3] = QPu[(r0 + 8) * APAD + kc + 4];
#pragma unroll
            for (int nt = 0; nt < 8; nt++) {
                int rn = nt * 8 + gid;      // d index
                uint32_t b0 = Vsu[kc * APAD + rn];
                uint32_t b1 = Vsu[(kc + 4) * APAD + rn];
                mma_tf32(oa[nt], pa, b0, b1);
            }
        }
    }

    // ---- epilogue: reduce l over tig group, normalize, store ----
    l0 += __shfl_xor_sync(0xffffffff, l0, 1);
    l0 += __shfl_xor_sync(0xffffffff, l0, 2);
    l1 += __shfl_xor_sync(0xffffffff, l1, 1);
    l1 += __shfl_xor_sync(0xffffffff, l1, 2);
    float inv0 = 1.f / l0, inv1 = 1.f / l1;

    size_t row0 = (size_t)(b * S + qbase + r0);
#pragma unroll
    for (int nt = 0; nt < 8; nt++) {
        int col = h * 64 + nt * 8 + tig * 2;
        *(float2*)&attn[row0 * D + col] =
            make_float2(oa[nt][0] * inv0, oa[nt][1] * inv0);
        *(float2*)&attn[(row0 + 8) * D + col] =
            make_float2(oa[nt][2] * inv1, oa[nt][3] * inv1);
    }
}

extern "C" void kernel_launch(void* const* d_in, const int* in_sizes, int n_in,
                              void* d_out, int out_size) {
    const float* x    = (const float*)d_in[0];   // [4,2048,1024]
    const float* Wqkv = (const float*)d_in[1];   // [3072,1024]
    const float* Wout = (const float*)d_in[2];   // [1024,1024]
    float* out = (float*)d_out;                  // [4,2048,1024]

    float* qkv;
    float* attn;
    cudaGetSymbolAddress((void**)&qkv, g_qkv);
    cudaGetSymbolAddress((void**)&attn, g_attn);

    cudaFuncSetAttribute(gemm_mma<true>, cudaFuncAttributeMaxDynamicSharedMemorySize,
                         GEMM_SMEM_BYTES);
    cudaFuncSetAttribute(gemm_mma<false>, cudaFuncAttributeMaxDynamicSharedMemorySize,
                         GEMM_SMEM_BYTES);
    cudaFuncSetAttribute(attn_mma, cudaFuncAttributeMaxDynamicSharedMemorySize,
                         ATT_SMEM_BYTES);

    // qkv = x @ Wqkv^T (output pre-rounded to tf32 for the attention mmas)
    gemm_mma<true><<<dim3(3072 / 128, 8192 / 128), 256, GEMM_SMEM_BYTES>>>(
        x, Wqkv, qkv, 8192, 3072, 1024);
    // causal MHA (tf32 mma)
    attn_mma<<<dim3(16, 16, 4), 256, ATT_SMEM_BYTES>>>(qkv, attn);
    // out = attn @ Wout^T (full fp32 store)
    gemm_mma<false><<<dim3(1024 / 128, 8192 / 128), 256, GEMM_SMEM_BYTES>>>(
        attn, Wout, out, 8192, 1024, 1024);
}

// round 13
// speedup vs baseline: 3.4328x; 1.0490x over previous
#include <cuda_runtime.h>
#include <cuda_bf16.h>
#include <math.h>
#include <cstdint>

// Scratch (no cudaMalloc allowed)
__device__ float g_qkv[4L * 2048 * 3072];    // tf32-rounded qkv
__device__ float g_attn[4L * 2048 * 1024];   // tf32-rounded attention out
__device__ float g_xr[8192L * 1024];         // tf32-rounded x
__device__ float g_wqkvr[3072L * 1024];      // tf32-rounded W_qkv
__device__ float g_woutr[1024L * 1024];      // tf32-rounded W_out

// ===========================================================================
// helpers (sm_103 base target only — tcgen05/TMEM unavailable in this devloop)
// ===========================================================================
__device__ __forceinline__ uint32_t smem_to_u32(const void* p) {
    uint32_t a;
    asm("{ .reg .u64 t; cvta.to.shared.u64 t, %1; cvt.u32.u64 %0, t; }"
        : "=r"(a) : "l"(p));
    return a;
}

__device__ __forceinline__ void cp_async16(uint32_t dst, const void* src) {
    asm volatile("cp.async.cg.shared.global [%0], [%1], 16;" :: "r"(dst), "l"(src));
}
#define CP_COMMIT() asm volatile("cp.async.commit_group;" ::: "memory")
#define CP_WAIT(n)  asm volatile("cp.async.wait_group %0;" :: "n"(n) : "memory")

__device__ __forceinline__ uint32_t f2tf32(float f) {
    uint32_t r;
    asm("cvt.rna.tf32.f32 %0, %1;" : "=r"(r) : "f"(f));
    return r;
}

__device__ __forceinline__ void mma_tf32(float* c, const uint32_t* a,
                                         uint32_t b0, uint32_t b1) {
    asm volatile(
        "mma.sync.aligned.m16n8k8.row.col.f32.tf32.tf32.f32 "
        "{%0,%1,%2,%3}, {%4,%5,%6,%7}, {%8,%9}, {%0,%1,%2,%3};"
        : "+f"(c[0]), "+f"(c[1]), "+f"(c[2]), "+f"(c[3])
        : "r"(a[0]), "r"(a[1]), "r"(a[2]), "r"(a[3]), "r"(b0), "r"(b1));
}

// elementwise rna-round to tf32 (float4 per thread)
__global__ __launch_bounds__(256) void round_tf32(const float* __restrict__ in,
                                                  float* __restrict__ out, int n4) {
    int i = blockIdx.x * 256 + threadIdx.x;
    if (i < n4) {
        float4 v = ((const float4*)in)[i];
        v.x = __uint_as_float(f2tf32(v.x));
        v.y = __uint_as_float(f2tf32(v.y));
        v.z = __uint_as_float(f2tf32(v.z));
        v.w = __uint_as_float(f2tf32(v.w));
        ((float4*)out)[i] = v;
    }
}

// ===========================================================================
// tf32 mma.sync GEMM: C[M,N] = A[M,K] * B[N,K]^T ; inputs PRE-ROUNDED to tf32.
// CTA 128x128, BK=32, 256 threads (8 warps, 32m x 64n), double-buffered.
// Smem: 128B rows, XOR-on-row-parity swizzle; k-permuted fragments so every
// fragment gather is one LDS.128 (conflict-free). No cvt in inner loop.
// ===========================================================================
static constexpr int TILE_F = 128 * 32;                  // floats per tile
static constexpr int BUF_F  = 2 * TILE_F;                // A+B per stage
static constexpr int GEMM_SMEM_BYTES = 2 * BUF_F * 4;    // 65536

template <bool CVT_OUT>
__global__ __launch_bounds__(256) void gemm_mma(const float* __restrict__ A,
                                                const float* __restrict__ B,
                                                float* __restrict__ C,
                                                int M, int N, int K) {
    extern __shared__ float smem[];
    uint32_t sb = smem_to_u32(smem);

    int tid  = threadIdx.x;
    int wid  = tid >> 5;
    int lane = tid & 31;
    int gid  = lane >> 2;
    int tig  = lane & 3;
    int wm   = wid & 3;
    int wn   = wid >> 2;
    int bm   = blockIdx.y * 128;
    int bn   = blockIdx.x * 128;

    const int n_iters = K / 32;

    // cp.async: row r (128B), chunk c16; dst col XOR-swizzled by row parity
    auto load_tile = [&](int it, int buf) {
        uint32_t abase = sb + (uint32_t)buf * (BUF_F * 4);
        uint32_t bbase = abase + TILE_F * 4;
        const char* Ab = (const char*)(A + (size_t)bm * K + (size_t)it * 32);
        const char* Bb = (const char*)(B + (size_t)bn * K + (size_t)it * 32);
#pragma unroll
        for (int i = 0; i < 4; i++) {
            int ch  = tid + i * 256;
            int r   = ch >> 3;
            int c16 = (ch & 7) * 16;
            uint32_t sc = (uint32_t)(c16 ^ ((r & 1) << 6));
            cp_async16(abase + r * 128 + sc, Ab + (size_t)r * K * 4 + c16);
            cp_async16(bbase + r * 128 + sc, Bb + (size_t)r * K * 4 + c16);
        }
        CP_COMMIT();
    };

    float acc[2][8][4];
#pragma unroll
    for (int mt = 0; mt < 2; mt++)
#pragma unroll
        for (int nt = 0; nt < 8; nt++)
#pragma unroll
            for (int j = 0; j < 4; j++) acc[mt][nt][j] = 0.f;

    load_tile(0, 0);

    for (int it = 0; it < n_iters; it++) {
        int buf = it & 1;
        if (it + 1 < n_iters) {
            load_tile(it + 1, buf ^ 1);
            CP_WAIT(1);
        } else {
            CP_WAIT(0);
        }
        __syncthreads();

        const float4* As4 = (const float4*)(smem + buf * BUF_F);
        const float4* Bs4 = As4 + TILE_F / 4;

        // k-pair p covers physical cols [16p,16p+16); thread tig owns 4 floats
        // at cols 16p+4*tig..+3 -> one float4, swizzle-XOR by row parity.
#pragma unroll
        for (int p = 0; p < 2; p++) {
            uint32_t a0[2][4], a1[2][4];
#pragma unroll
            for (int mt = 0; mt < 2; mt++) {
                int r = wm * 32 + mt * 16 + gid;
                int q = (p * 4 + tig) ^ ((r & 1) << 2);
                float4 lo = As4[r * 8 + q];
                float4 hi = As4[(r + 8) * 8 + q];
                a0[mt][0] = __float_as_uint(lo.x); a0[mt][1] = __float_as_uint(hi.x);
                a0[mt][2] = __float_as_uint(lo.y); a0[mt][3] = __float_as_uint(hi.y);
                a1[mt][0] = __float_as_uint(lo.z); a1[mt][1] = __float_as_uint(hi.z);
                a1[mt][2] = __float_as_uint(lo.w); a1[mt][3] = __float_as_uint(hi.w);
            }
#pragma unroll
            for (int nt = 0; nt < 8; nt++) {
                int rn = wn * 64 + nt * 8 + gid;
                int q  = (p * 4 + tig) ^ ((rn & 1) << 2);
                float4 bv = Bs4[rn * 8 + q];
                uint32_t b0 = __float_as_uint(bv.x), b1 = __float_as_uint(bv.y);
                uint32_t b2 = __float_as_uint(bv.z), b3 = __float_as_uint(bv.w);
                mma_tf32(acc[0][nt], a0[0], b0, b1);
                mma_tf32(acc[1][nt], a0[1], b0, b1);
                mma_tf32(acc[0][nt], a1[0], b2, b3);
                mma_tf32(acc[1][nt], a1[1], b2, b3);
            }
        }
        __syncthreads();
    }

#pragma unroll
    for (int mt = 0; mt < 2; mt++) {
        int row = bm + wm * 32 + mt * 16 + gid;
#pragma unroll
        for (int nt = 0; nt < 8; nt++) {
            int col = bn + wn * 64 + nt * 8 + tig * 2;
            float v0 = acc[mt][nt][0], v1 = acc[mt][nt][1];
            float v2 = acc[mt][nt][2], v3 = acc[mt][nt][3];
            if (CVT_OUT) {
                v0 = __uint_as_float(f2tf32(v0));
                v1 = __uint_as_float(f2tf32(v1));
                v2 = __uint_as_float(f2tf32(v2));
                v3 = __uint_as_float(f2tf32(v3));
            }
            *(float2*)&C[(size_t)row * N + col] = make_float2(v0, v1);
            *(float2*)&C[(size_t)(row + 8) * N + col] = make_float2(v2, v3);
        }
    }
}

// ===========================================================================
// Causal flash attention with tf32 mma.sync (unchanged from R9 except the
// epilogue stores tf32-rounded O so GEMM2 can do raw loads). hd=64.
// ===========================================================================
static constexpr int APAD = 68;
static constexpr int ATT_QP_F = 128 * APAD;
static constexpr int ATT_K_F  = 64 * APAD;
static constexpr int ATT_SMEM_BYTES = (ATT_QP_F + 2 * ATT_K_F) * 4;   // 69632

__global__ __launch_bounds__(256, 2) void attn_mma(const float* __restrict__ qkv,
                                                   float* __restrict__ attn) {
    const int S = 2048, TD = 3072, D = 1024;
    extern __shared__ float sm[];
    float* QP = sm;
    float* Ks = sm + ATT_QP_F;
    float* Vs = Ks + ATT_K_F;
    const uint32_t* QPu = (const uint32_t*)QP;
    const uint32_t* Ksu = (const uint32_t*)Ks;
    const uint32_t* Vsu = (const uint32_t*)Vs;

    uint32_t sb = smem_to_u32(sm);
    const uint32_t sbK = sb + ATT_QP_F * 4;
    const uint32_t sbV = sbK + ATT_K_F * 4;

    int tid  = threadIdx.x;
    int wid  = tid >> 5;
    int lane = tid & 31;
    int gid  = lane >> 2;
    int tig  = lane & 3;
    int qt = blockIdx.x, h = blockIdx.y, b = blockIdx.z;
    int qbase = qt * 128;
    int r0 = wid * 16 + gid;

    {
        const char* Qg = (const char*)(qkv + (size_t)(b * S + qbase) * TD + h * 64);
#pragma unroll
        for (int i = 0; i < 8; i++) {
            int ch  = tid + i * 256;
            int r   = ch >> 4;
            int c16 = (ch & 15) * 16;
            cp_async16(sb + r * (APAD * 4) + c16, Qg + (size_t)r * TD * 4 + c16);
        }
        CP_COMMIT();
        CP_WAIT(0);
        __syncthreads();
    }

    uint32_t qa[8][4];
#pragma unroll
    for (int ks = 0; ks < 8; ks++) {
        int kc = ks * 8 + tig;
        qa[ks][0] = __float_as_uint(0.125f * QP[r0 * APAD + kc]);
        qa[ks][1] = __float_as_uint(0.125f * QP[(r0 + 8) * APAD + kc]);
        qa[ks][2] = __float_as_uint(0.125f * QP[r0 * APAD + kc + 4]);
        qa[ks][3] = __float_as_uint(0.125f * QP[(r0 + 8) * APAD + kc + 4]);
    }
    __syncthreads();

    float oa[8][4];
#pragma unroll
    for (int nt = 0; nt < 8; nt++)
#pragma unroll
        for (int j = 0; j < 4; j++) oa[nt][j] = 0.f;
    float m0 = -1e30f, m1 = -1e30f, l0 = 0.f, l1 = 0.f;

    const int qg0 = qbase + r0;
    const int qg1 = qg0 + 8;
    const int ktmax = 2 * qt + 1;

    for (int kt = 0; kt <= ktmax; kt++) {
        int kb = kt * 64;
        __syncthreads();

        const char* Kg = (const char*)(qkv + (size_t)(b * S + kb) * TD + 1024 + h * 64);
        const char* Vg = (const char*)(qkv + (size_t)(b * S + kb) * TD + 2048 + h * 64);
#pragma unroll
        for (int i = 0; i < 4; i++) {
            int ch  = tid + i * 256;
            int r   = ch >> 4;
            int c16 = (ch & 15) * 16;
            cp_async16(sbK + r * (APAD * 4) + c16, Kg + (size_t)r * TD * 4 + c16);
            cp_async16(sbV + r * (APAD * 4) + c16, Vg + (size_t)r * TD * 4 + c16);
        }
        CP_COMMIT();
        CP_WAIT(0);
        __syncthreads();

        float sa[8][4];
#pragma unroll
        for (int nt = 0; nt < 8; nt++)
#pragma unroll
            for (int j = 0; j < 4; j++) sa[nt][j] = 0.f;
#pragma unroll
        for (int ks = 0; ks < 8; ks++) {
            int kc = ks * 8 + tig;
#pragma unroll
            for (int nt = 0; nt < 8; nt++) {
                int rn = nt * 8 + gid;
                uint32_t b0 = Ksu[rn * APAD + kc];
                uint32_t b1 = Ksu[rn * APAD + kc + 4];
                mma_tf32(sa[nt], qa[ks], b0, b1);
            }
        }

        if (kt >= 2 * qt) {
#pragma unroll
            for (int nt = 0; nt < 8; nt++) {
                int kg = kb + nt * 8 + tig * 2;
                if (kg > qg0)     sa[nt][0] = -1e30f;
                if (kg + 1 > qg0) sa[nt][1] = -1e30f;
                if (kg > qg1)     sa[nt][2] = -1e30f;
                if (kg + 1 > qg1) sa[nt][3] = -1e30f;
            }
        }

        float v0 = -1e30f, v1 = -1e30f;
#pragma unroll
        for (int nt = 0; nt < 8; nt++) {
            v0 = fmaxf(v0, fmaxf(sa[nt][0], sa[nt][1]));
            v1 = fmaxf(v1, fmaxf(sa[nt][2], sa[nt][3]));
        }
        v0 = fmaxf(v0, __shfl_xor_sync(0xffffffff, v0, 1));
        v0 = fmaxf(v0, __shfl_xor_sync(0xffffffff, v0, 2));
        v1 = fmaxf(v1, __shfl_xor_sync(0xffffffff, v1, 1));
        v1 = fmaxf(v1, __shfl_xor_sync(0xffffffff, v1, 2));
        float mn0 = fmaxf(m0, v0), mn1 = fmaxf(m1, v1);
        float f0 = __expf(m0 - mn0), f1 = __expf(m1 - mn1);
        m0 = mn0; m1 = mn1;

        float ls0 = 0.f, ls1 = 0.f;
#pragma unroll
        for (int nt = 0; nt < 8; nt++) {
            int col = nt * 8 + tig * 2;
            float p00 = __expf(sa[nt][0] - mn0);
            float p01 = __expf(sa[nt][1] - mn0);
            float p10 = __expf(sa[nt][2] - mn1);
            float p11 = __expf(sa[nt][3] - mn1);
            ls0 += p00 + p01;
            ls1 += p10 + p11;
            QP[r0 * APAD + col]       = __uint_as_float(f2tf32(p00));
            QP[r0 * APAD + col + 1]   = __uint_as_float(f2tf32(p01));
            QP[(r0 + 8) * APAD + col]     = __uint_as_float(f2tf32(p10));
            QP[(r0 + 8) * APAD + col + 1] = __uint_as_float(f2tf32(p11));
        }
        l0 = l0 * f0 + ls0;
        l1 = l1 * f1 + ls1;
#pragma unroll
        for (int nt = 0; nt < 8; nt++) {
            oa[nt][0] *= f0; oa[nt][1] *= f0;
            oa[nt][2] *= f1; oa[nt][3] *= f1;
        }
        __syncwarp();

#pragma unroll
        for (int ks = 0; ks < 8; ks++) {
            int kc = ks * 8 + tig;
            uint32_t pa[4];
            pa[0] = QPu[r0 * APAD + kc];
            pa[1] = QPu[(r0 + 8) * APAD + kc];
            pa[2] = QPu[r0 * APAD + kc + 4];
            pa[3] = QPu[(r0 + 8) * APAD + kc + 4];
#pragma unroll
            for (int nt = 0; nt < 8; nt++) {
                int rn = nt * 8 + gid;
                uint32_t b0 = Vsu[kc * APAD + rn];
                uint32_t b1 = Vsu[(kc + 4) * APAD + rn];
                mma_tf32(oa[nt], pa, b0, b1);
            }
        }
    }

    l0 += __shfl_xor_sync(0xffffffff, l0, 1);
    l0 += __shfl_xor_sync(0xffffffff, l0, 2);
    l1 += __shfl_xor_sync(0xffffffff, l1, 1);
    l1 += __shfl_xor_sync(0xffffffff, l1, 2);
    float inv0 = 1.f / l0, inv1 = 1.f / l1;

    size_t row0 = (size_t)(b * S + qbase + r0);
#pragma unroll
    for (int nt = 0; nt < 8; nt++) {
        int col = h * 64 + nt * 8 + tig * 2;
        // store pre-rounded tf32 (GEMM2 loads raw; same rna GEMM2 would apply)
        *(float2*)&attn[row0 * D + col] = make_float2(
            __uint_as_float(f2tf32(oa[nt][0] * inv0)),
            __uint_as_float(f2tf32(oa[nt][1] * inv0)));
        *(float2*)&attn[(row0 + 8) * D + col] = make_float2(
            __uint_as_float(f2tf32(oa[nt][2] * inv1)),
            __uint_as_float(f2tf32(oa[nt][3] * inv1)));
    }
}

extern "C" void kernel_launch(void* const* d_in, const int* in_sizes, int n_in,
                              void* d_out, int out_size) {
    const float* x    = (const float*)d_in[0];   // [4,2048,1024]
    const float* Wqkv = (const float*)d_in[1];   // [3072,1024]
    const float* Wout = (const float*)d_in[2];   // [1024,1024]
    float* out = (float*)d_out;                  // [4,2048,1024]

    float *qkv, *attn, *xr, *wqkvr, *woutr;
    cudaGetSymbolAddress((void**)&qkv, g_qkv);
    cudaGetSymbolAddress((void**)&attn, g_attn);
    cudaGetSymbolAddress((void**)&xr, g_xr);
    cudaGetSymbolAddress((void**)&wqkvr, g_wqkvr);
    cudaGetSymbolAddress((void**)&woutr, g_woutr);

    cudaFuncSetAttribute(gemm_mma<true>, cudaFuncAttributeMaxDynamicSharedMemorySize,
                         GEMM_SMEM_BYTES);
    cudaFuncSetAttribute(gemm_mma<false>, cudaFuncAttributeMaxDynamicSharedMemorySize,
                         GEMM_SMEM_BYTES);
    cudaFuncSetAttribute(attn_mma, cudaFuncAttributeMaxDynamicSharedMemorySize,
                         ATT_SMEM_BYTES);

    // pre-round inputs to tf32 (rna) once
    round_tf32<<<(8192 * 1024 / 4 + 255) / 256, 256>>>(x, xr, 8192 * 1024 / 4);
    round_tf32<<<(3072 * 1024 / 4 + 255) / 256, 256>>>(Wqkv, wqkvr, 3072 * 1024 / 4);
    round_tf32<<<(1024 * 1024 / 4 + 255) / 256, 256>>>(Wout, woutr, 1024 * 1024 / 4);

    // qkv = x @ Wqkv^T (tf32 out for attention raw loads)
    gemm_mma<true><<<dim3(3072 / 128, 8192 / 128), 256, GEMM_SMEM_BYTES>>>(
        xr, wqkvr, qkv, 8192, 3072, 1024);
    // causal MHA
    attn_mma<<<dim3(16, 16, 4), 256, ATT_SMEM_BYTES>>>(qkv, attn);
    // out = attn @ Wout^T (fp32 out)
    gemm_mma<false><<<dim3(1024 / 128, 8192 / 128), 256, GEMM_SMEM_BYTES>>>(
        attn, woutr, out, 8192, 1024, 1024);
}